// round 9
// baseline (speedup 1.0000x reference)
#include <cuda_runtime.h>
#include <cuda_bf16.h>
#include <math.h>
#include <stdint.h>

// ---------------- problem constants ----------------
#define B   16
#define S   256
#define NV  196
#define D   768
#define FF  2048
#define VOC 30522
#define NL  6
#define NH  8
#define HD  96          // D / NH
#define MX  (B*S)       // 4096 rows of x
#define MKV (B*NV)      // 3136 rows of fv
#define MDEC (B*(S-1))  // 4080 rows of dec

// ---------------- scratch (device globals; no allocation) ----------------
__device__ float g_x   [MX * D];
__device__ float g_qkv [MX * 3*D];
__device__ float g_attn[MX * D];
__device__ float g_y   [MX * D];
__device__ float g_q   [MX * D];
__device__ float g_kv  [MKV * 2*D];
__device__ float g_dec [MDEC * D];

// ---------------- helpers ----------------
__device__ __forceinline__ float to_tf32(float x) {
    uint32_t u;
    asm("cvt.rna.tf32.f32 %0, %1;" : "=r"(u) : "f"(x));
    return __uint_as_float(u);
}

__device__ __forceinline__ void mma_tf32(float c[4],
    uint32_t a0, uint32_t a1, uint32_t a2, uint32_t a3,
    uint32_t b0, uint32_t b1)
{
    asm volatile(
        "mma.sync.aligned.m16n8k8.row.col.f32.tf32.tf32.f32 "
        "{%0,%1,%2,%3},{%4,%5,%6,%7},{%8,%9},{%0,%1,%2,%3};\n"
        : "+f"(c[0]), "+f"(c[1]), "+f"(c[2]), "+f"(c[3])
        : "r"(a0), "r"(a1), "r"(a2), "r"(a3), "r"(b0), "r"(b1));
}

// ---------------- add positional encoding ----------------
__global__ void add_pe_kernel(float* __restrict__ x, const float* __restrict__ te) {
    int row = blockIdx.x;
    int s   = row % S;
    int tid = threadIdx.x;
    size_t base = (size_t)row * D;
    #pragma unroll
    for (int i = 0; i < 3; i++) {
        int d = tid + i * 256;
        int i2 = d & ~1;
        float div = expf(-(float)i2 * (9.210340371976184f / (float)D));
        float ang = (float)s * div;
        float pe  = (d & 1) ? cosf(ang) : sinf(ang);
        x[base + d] = te[base + d] + pe;
    }
}

// ---------------- TF32 tensor-core GEMM, double-buffered smem ----------------
// C[m][n] = sum_k A[m][k]*W[n][k] + bias[n] ; optional relu.
// Block tile 128x128, BK=32, 8 warps (2x4), warp tile 64x32.
// K must be a multiple of 32 (768, 2048 both are).
#define BM 128
#define BN 128
#define BK 32
#define LDK (BK + 4)          // 36 floats/row: 36 % 32 == 4 -> conflict-free fragments
#define SMS (BM * LDK)        // floats per operand per stage
#define GEMM_SMEM_BYTES (4 * SMS * sizeof(float))   // A0 A1 B0 B1

__global__ __launch_bounds__(256) void tf32_gemm_kernel(
    const float* __restrict__ A, const float* __restrict__ W,
    const float* __restrict__ bias, float* __restrict__ C,
    int M, int N, int K, int relu)
{
    extern __shared__ float sm[];
    // layout: [A stage0][A stage1][B stage0][B stage1]
    float* Abuf[2] = { sm,           sm + SMS };
    float* Bbuf[2] = { sm + 2*SMS,   sm + 3*SMS };

    int tid  = threadIdx.x;
    int lane = tid & 31;
    int wid  = tid >> 5;
    int gid  = lane >> 2;     // group id 0..7
    int tig  = lane & 3;      // thread in group 0..3
    int wm   = wid >> 2;      // 0..1  -> m offset wm*64
    int wn   = wid & 3;       // 0..3  -> n offset wn*32

    int row0 = blockIdx.y * BM;
    int col0 = blockIdx.x * BN;

    // loader mapping: 128 rows x 8 float4 (BK=32) = 1024 float4 per operand; 4 per thread
    int lrow[4], lkv[4];
    #pragma unroll
    for (int i = 0; i < 4; i++) { int idx = i * 256 + tid; lrow[i] = idx >> 3; lkv[i] = idx & 7; }

    float4 ra[4], rb[4];

    // ---- prologue: load tile 0 -> regs -> stage 0 ----
    #pragma unroll
    for (int i = 0; i < 4; i++) {
        int gr = row0 + lrow[i];
        int gk = lkv[i] * 4;
        if (gr < M) ra[i] = *(const float4*)&A[(size_t)gr * K + gk];
        else        ra[i] = make_float4(0.f, 0.f, 0.f, 0.f);
        int gn = col0 + lrow[i];
        if (gn < N) rb[i] = *(const float4*)&W[(size_t)gn * K + gk];
        else        rb[i] = make_float4(0.f, 0.f, 0.f, 0.f);
    }
    #pragma unroll
    for (int i = 0; i < 4; i++) {
        float4 a4 = ra[i], b4 = rb[i];
        a4.x = to_tf32(a4.x); a4.y = to_tf32(a4.y); a4.z = to_tf32(a4.z); a4.w = to_tf32(a4.w);
        b4.x = to_tf32(b4.x); b4.y = to_tf32(b4.y); b4.z = to_tf32(b4.z); b4.w = to_tf32(b4.w);
        *(float4*)&Abuf[0][lrow[i] * LDK + lkv[i] * 4] = a4;
        *(float4*)&Bbuf[0][lrow[i] * LDK + lkv[i] * 4] = b4;
    }
    __syncthreads();

    float acc[4][4][4] = {};   // [mtile][ntile][reg]
    int nT = K / BK;
    int stage = 0;

    for (int t = 0; t < nT; t++) {
        // prefetch next tile global -> regs (latency hidden under compute)
        if (t + 1 < nT) {
            int kb = (t + 1) * BK;
            #pragma unroll
            for (int i = 0; i < 4; i++) {
                int gr = row0 + lrow[i];
                int gk = kb + lkv[i] * 4;
                if (gr < M) ra[i] = *(const float4*)&A[(size_t)gr * K + gk];
                else        ra[i] = make_float4(0.f, 0.f, 0.f, 0.f);
                int gn = col0 + lrow[i];
                if (gn < N) rb[i] = *(const float4*)&W[(size_t)gn * K + gk];
                else        rb[i] = make_float4(0.f, 0.f, 0.f, 0.f);
            }
        }

        // compute from current stage
        const float* As = Abuf[stage];
        const float* Bs = Bbuf[stage];
        #pragma unroll
        for (int kk = 0; kk < BK; kk += 8) {
            uint32_t af[4][4];
            #pragma unroll
            for (int mt = 0; mt < 4; mt++) {
                int rbase = wm * 64 + mt * 16;
                af[mt][0] = __float_as_uint(As[(rbase + gid)     * LDK + kk + tig]);
                af[mt][1] = __float_as_uint(As[(rbase + gid + 8) * LDK + kk + tig]);
                af[mt][2] = __float_as_uint(As[(rbase + gid)     * LDK + kk + tig + 4]);
                af[mt][3] = __float_as_uint(As[(rbase + gid + 8) * LDK + kk + tig + 4]);
            }
            uint32_t bf[4][2];
            #pragma unroll
            for (int nt = 0; nt < 4; nt++) {
                int cbase = wn * 32 + nt * 8;
                bf[nt][0] = __float_as_uint(Bs[(cbase + gid) * LDK + kk + tig]);
                bf[nt][1] = __float_as_uint(Bs[(cbase + gid) * LDK + kk + tig + 4]);
            }
            #pragma unroll
            for (int mt = 0; mt < 4; mt++)
                #pragma unroll
                for (int nt = 0; nt < 4; nt++)
                    mma_tf32(acc[mt][nt], af[mt][0], af[mt][1], af[mt][2], af[mt][3],
                             bf[nt][0], bf[nt][1]);
        }

        // store prefetched regs into the other stage (nobody reads it this iter)
        if (t + 1 < nT) {
            int nxt = stage ^ 1;
            #pragma unroll
            for (int i = 0; i < 4; i++) {
                float4 a4 = ra[i], b4 = rb[i];
                a4.x = to_tf32(a4.x); a4.y = to_tf32(a4.y); a4.z = to_tf32(a4.z); a4.w = to_tf32(a4.w);
                b4.x = to_tf32(b4.x); b4.y = to_tf32(b4.y); b4.z = to_tf32(b4.z); b4.w = to_tf32(b4.w);
                *(float4*)&Abuf[nxt][lrow[i] * LDK + lkv[i] * 4] = a4;
                *(float4*)&Bbuf[nxt][lrow[i] * LDK + lkv[i] * 4] = b4;
            }
        }
        __syncthreads();
        stage ^= 1;
    }

    // epilogue: c0:(gid, 2tig) c1:(gid, 2tig+1) c2:(gid+8, 2tig) c3:(gid+8, 2tig+1)
    #pragma unroll
    for (int mt = 0; mt < 4; mt++) {
        int r_lo = row0 + wm * 64 + mt * 16 + gid;
        int r_hi = r_lo + 8;
        #pragma unroll
        for (int nt = 0; nt < 4; nt++) {
            int gn = col0 + wn * 32 + nt * 8 + 2 * tig;
            if (gn >= N) continue;
            float b0 = bias ? bias[gn]     : 0.f;
            float b1 = bias ? bias[gn + 1] : 0.f;
            if (r_lo < M) {
                float v0 = acc[mt][nt][0] + b0;
                float v1 = acc[mt][nt][1] + b1;
                if (relu) { v0 = fmaxf(v0, 0.f); v1 = fmaxf(v1, 0.f); }
                *(float2*)&C[(size_t)r_lo * N + gn] = make_float2(v0, v1);
            }
            if (r_hi < M) {
                float v2 = acc[mt][nt][2] + b0;
                float v3 = acc[mt][nt][3] + b1;
                if (relu) { v2 = fmaxf(v2, 0.f); v3 = fmaxf(v3, 0.f); }
                *(float2*)&C[(size_t)r_hi * N + gn] = make_float2(v2, v3);
            }
        }
    }
}

static inline void launch_gemm(const float* A, const float* W, const float* bias,
                               float* C, int M, int N, int K, int relu) {
    dim3 grid((N + BN - 1) / BN, (M + BM - 1) / BM);
    tf32_gemm_kernel<<<grid, 256, GEMM_SMEM_BYTES>>>(A, W, bias, C, M, N, K, relu);
}

// ---------------- flash attention: 32-q x 32-k tiles, online softmax ----------------
#define QT 32
#define KT 32
__global__ __launch_bounds__(256) void flash_attn_kernel(
    const float* __restrict__ Q, int q_stride,
    const float* __restrict__ KV, int kv_stride, int k_off, int v_off,
    float* __restrict__ O,
    int Lq, int Lk, int causal, float scale)
{
    __shared__ float Qs[QT][HD + 1];
    __shared__ float Ks[KT][HD + 1];
    __shared__ float Vs[KT][HD + 1];
    int bh = blockIdx.y;
    int b = bh >> 3, h = bh & 7;
    int q0 = blockIdx.x * QT;
    int tid = threadIdx.x;
    int qr = tid >> 3;         // 0..31 query row in tile
    int sub = tid & 7;         // 8 threads per row
    int qi = q0 + qr;

    const float* qbase = Q + (size_t)(b * Lq + q0) * q_stride + h * HD;
    for (int i = tid; i < QT * HD; i += 256) {
        int r = i / HD, d = i % HD;
        Qs[r][d] = qbase[(size_t)r * q_stride + d];
    }
    __syncthreads();

    const float* kbase = KV + (size_t)b * Lk * kv_stride + k_off + h * HD;
    const float* vbase = KV + (size_t)b * Lk * kv_stride + v_off + h * HD;

    float m = -1e30f, lsum = 0.f;
    float o[12];
    #pragma unroll
    for (int j = 0; j < 12; j++) o[j] = 0.f;

    int kend = causal ? (q0 + QT < Lk ? q0 + QT : Lk) : Lk;
    int lanebase = (tid & 31) & ~7;

    for (int k0 = 0; k0 < kend; k0 += KT) {
        for (int i = tid; i < KT * HD; i += 256) {
            int r = i / HD, d = i % HD;
            int ki = k0 + r;
            if (ki < Lk) {
                Ks[r][d] = kbase[(size_t)ki * kv_stride + d];
                Vs[r][d] = vbase[(size_t)ki * kv_stride + d];
            } else {
                Ks[r][d] = 0.f;
                Vs[r][d] = 0.f;
            }
        }
        __syncthreads();

        float sc[4];
        #pragma unroll
        for (int c = 0; c < 4; c++) {
            int kk = sub * 4 + c;
            int ki = k0 + kk;
            float acc = 0.f;
            #pragma unroll
            for (int d = 0; d < HD; d += 4) {
                acc = fmaf(Qs[qr][d + 0], Ks[kk][d + 0], acc);
                acc = fmaf(Qs[qr][d + 1], Ks[kk][d + 1], acc);
                acc = fmaf(Qs[qr][d + 2], Ks[kk][d + 2], acc);
                acc = fmaf(Qs[qr][d + 3], Ks[kk][d + 3], acc);
            }
            acc *= scale;
            if (ki >= Lk || (causal && ki > qi)) acc = -1e30f;
            sc[c] = acc;
        }
        float tm = fmaxf(fmaxf(sc[0], sc[1]), fmaxf(sc[2], sc[3]));
        #pragma unroll
        for (int off = 4; off; off >>= 1) tm = fmaxf(tm, __shfl_xor_sync(~0u, tm, off));
        float mnew = fmaxf(m, tm);
        float corr = __expf(m - mnew);
        float p[4];
        float psum = 0.f;
        #pragma unroll
        for (int c = 0; c < 4; c++) { p[c] = __expf(sc[c] - mnew); psum += p[c]; }
        #pragma unroll
        for (int off = 4; off; off >>= 1) psum += __shfl_xor_sync(~0u, psum, off);
        lsum = lsum * corr + psum;
        #pragma unroll
        for (int j = 0; j < 12; j++) o[j] *= corr;
        m = mnew;
        #pragma unroll
        for (int kk = 0; kk < KT; kk++) {
            float pv = __shfl_sync(~0u, p[kk & 3], lanebase + (kk >> 2));
            #pragma unroll
            for (int j = 0; j < 12; j++)
                o[j] = fmaf(pv, Vs[kk][sub * 12 + j], o[j]);
        }
        __syncthreads();
    }

    float inv = 1.f / lsum;
    float* orow = O + (size_t)(b * Lq + qi) * D + h * HD + sub * 12;
    #pragma unroll
    for (int j = 0; j < 12; j++) orow[j] = o[j] * inv;
}

// ---------------- fused residual + layernorm ----------------
__global__ __launch_bounds__(256) void residual_ln_kernel(
    float* __restrict__ X, const float* __restrict__ Y,
    const float* __restrict__ w, const float* __restrict__ b)
{
    __shared__ float red[8];
    int row = blockIdx.x;
    int tid = threadIdx.x;
    size_t base = (size_t)row * D;
    float v0 = X[base + tid]       + Y[base + tid];
    float v1 = X[base + tid + 256] + Y[base + tid + 256];
    float v2 = X[base + tid + 512] + Y[base + tid + 512];
    float s = v0 + v1 + v2;
    #pragma unroll
    for (int off = 16; off; off >>= 1) s += __shfl_xor_sync(~0u, s, off);
    if ((tid & 31) == 0) red[tid >> 5] = s;
    __syncthreads();
    float tot = 0.f;
    #pragma unroll
    for (int i = 0; i < 8; i++) tot += red[i];
    float mean = tot * (1.f / (float)D);
    float d0 = v0 - mean, d1 = v1 - mean, d2 = v2 - mean;
    float q = d0 * d0 + d1 * d1 + d2 * d2;
    #pragma unroll
    for (int off = 16; off; off >>= 1) q += __shfl_xor_sync(~0u, q, off);
    __syncthreads();
    if ((tid & 31) == 0) red[tid >> 5] = q;
    __syncthreads();
    float vq = 0.f;
    #pragma unroll
    for (int i = 0; i < 8; i++) vq += red[i];
    float var = vq * (1.f / (float)D);
    float rs = rsqrtf(var + 1e-5f);
    X[base + tid]       = d0 * rs * w[tid]       + b[tid];
    X[base + tid + 256] = d1 * rs * w[tid + 256] + b[tid + 256];
    X[base + tid + 512] = d2 * rs * w[tid + 512] + b[tid + 512];
}

// ---------------- dec copy ----------------
__global__ void copy_dec_kernel(float* __restrict__ dec, const float* __restrict__ x) {
    int r   = blockIdx.x;
    int b   = r / (S - 1);
    int s   = r % (S - 1);
    int tid = threadIdx.x;
    size_t src = (size_t)(b * S + s) * D;
    size_t dst = (size_t)r * D;
    #pragma unroll
    for (int i = 0; i < 3; i++) dec[dst + tid + i * 256] = x[src + tid + i * 256];
}

// ---------------- row softmax over D for F_t ----------------
__global__ __launch_bounds__(256) void softmax_rows_kernel(
    const float* __restrict__ X, float* __restrict__ O)
{
    __shared__ float red[8];
    int row = blockIdx.x;
    int tid = threadIdx.x;
    size_t base = (size_t)row * D;
    float v0 = X[base + tid], v1 = X[base + tid + 256], v2 = X[base + tid + 512];
    float m = fmaxf(fmaxf(v0, v1), v2);
    #pragma unroll
    for (int off = 16; off; off >>= 1) m = fmaxf(m, __shfl_xor_sync(~0u, m, off));
    if ((tid & 31) == 0) red[tid >> 5] = m;
    __syncthreads();
    float gm = red[0];
    #pragma unroll
    for (int i = 1; i < 8; i++) gm = fmaxf(gm, red[i]);
    float e0 = expf(v0 - gm), e1 = expf(v1 - gm), e2 = expf(v2 - gm);
    float s = e0 + e1 + e2;
    #pragma unroll
    for (int off = 16; off; off >>= 1) s += __shfl_xor_sync(~0u, s, off);
    __syncthreads();
    if ((tid & 31) == 0) red[tid >> 5] = s;
    __syncthreads();
    float tot = 0.f;
    #pragma unroll
    for (int i = 0; i < 8; i++) tot += red[i];
    float inv = 1.f / tot;
    O[base + tid]       = e0 * inv;
    O[base + tid + 256] = e1 * inv;
    O[base + tid + 512] = e2 * inv;
}

// ---------------- orchestration ----------------
extern "C" void kernel_launch(void* const* d_in, const int* in_sizes, int n_in,
                              void* d_out, int out_size)
{
    const float* fv          = (const float*)d_in[0];
    const float* target_embed= (const float*)d_in[1];
    const float* self_in_w   = (const float*)d_in[2];
    const float* self_in_b   = (const float*)d_in[3];
    const float* self_out_w  = (const float*)d_in[4];
    const float* self_out_b  = (const float*)d_in[5];
    const float* cross_in_w  = (const float*)d_in[6];
    const float* cross_in_b  = (const float*)d_in[7];
    const float* cross_out_w = (const float*)d_in[8];
    const float* cross_out_b = (const float*)d_in[9];
    const float* lin1_w      = (const float*)d_in[10];
    const float* lin1_b      = (const float*)d_in[11];
    const float* lin2_w      = (const float*)d_in[12];
    const float* lin2_b      = (const float*)d_in[13];
    const float* ln_w        = (const float*)d_in[14];
    const float* ln_b        = (const float*)d_in[15];
    const float* fc_out_w    = (const float*)d_in[16];
    float* out = (float*)d_out;

    // allow >48KB dynamic smem for the GEMM (host-side attribute; capture-safe)
    static int smem_attr_set = 0;
    if (!smem_attr_set) {
        cudaFuncSetAttribute(tf32_gemm_kernel,
                             cudaFuncAttributeMaxDynamicSharedMemorySize,
                             (int)GEMM_SMEM_BYTES);
        smem_attr_set = 1;
    }

    float *px, *pqkv, *pattn, *py, *pq, *pkv, *pdec;
    cudaGetSymbolAddress((void**)&px,   g_x);
    cudaGetSymbolAddress((void**)&pqkv, g_qkv);
    cudaGetSymbolAddress((void**)&pattn,g_attn);
    cudaGetSymbolAddress((void**)&py,   g_y);
    cudaGetSymbolAddress((void**)&pq,   g_q);
    cudaGetSymbolAddress((void**)&pkv,  g_kv);
    cudaGetSymbolAddress((void**)&pdec, g_dec);

    const float scale = rsqrtf((float)HD);

    add_pe_kernel<<<MX, 256>>>(px, target_embed);

    for (int l = 0; l < NL; l++) {
        const float* siw = self_in_w   + (size_t)l * 3*D * D;
        const float* sib = self_in_b   + (size_t)l * 3*D;
        const float* sow = self_out_w  + (size_t)l * D * D;
        const float* sob = self_out_b  + (size_t)l * D;
        const float* ciw = cross_in_w  + (size_t)l * 3*D * D;
        const float* cib = cross_in_b  + (size_t)l * 3*D;
        const float* cow = cross_out_w + (size_t)l * D * D;
        const float* cob = cross_out_b + (size_t)l * D;
        const float* l1w = lin1_w      + (size_t)l * FF * D;
        const float* l1b = lin1_b      + (size_t)l * FF;
        const float* l2w = lin2_w      + (size_t)l * D * FF;
        const float* l2b = lin2_b      + (size_t)l * D;
        const float* lnw = ln_w        + (size_t)l * 3 * D;
        const float* lnb = ln_b        + (size_t)l * 3 * D;

        // ---- self attention ----
        launch_gemm(px, siw, sib, pqkv, MX, 3*D, D, 0);
        flash_attn_kernel<<<dim3(S / QT, B * NH), 256>>>(
            pqkv, 3*D, pqkv, 3*D, D, 2*D, pattn, S, S, 1, scale);
        launch_gemm(pattn, sow, sob, py, MX, D, D, 0);
        residual_ln_kernel<<<MX, 256>>>(px, py, lnw + 0*D, lnb + 0*D);

        // ---- cross attention ----
        launch_gemm(px, ciw, cib, pq, MX, D, D, 0);
        launch_gemm(fv, ciw + (size_t)D*D, cib + D, pkv, MKV, 2*D, D, 0);
        flash_attn_kernel<<<dim3(S / QT, B * NH), 256>>>(
            pq, D, pkv, 2*D, 0, D, pattn, S, NV, 0, scale);
        launch_gemm(pattn, cow, cob, py, MX, D, D, 0);
        residual_ln_kernel<<<MX, 256>>>(px, py, lnw + 1*D, lnb + 1*D);

        // ---- feed forward ----
        launch_gemm(px, l1w, l1b, pqkv, MX, FF, D, 1);
        launch_gemm(pqkv, l2w, l2b, py, MX, D, FF, 0);
        residual_ln_kernel<<<MX, 256>>>(px, py, lnw + 2*D, lnb + 2*D);
    }

    // ---- final heads ----
    copy_dec_kernel<<<MDEC, 256>>>(pdec, px);
    launch_gemm(pdec, fc_out_w, nullptr, out, MDEC, VOC, D, 0);
    softmax_rows_kernel<<<MDEC, 256>>>(pdec, out + (size_t)MDEC * VOC);
}

// round 10
// speedup vs baseline: 1.3617x; 1.3617x over previous
#include <cuda_runtime.h>
#include <cuda_bf16.h>
#include <math.h>
#include <stdint.h>

// ---------------- problem constants ----------------
#define B   16
#define S   256
#define NV  196
#define D   768
#define FF  2048
#define VOC 30522
#define NL  6
#define NH  8
#define HD  96          // D / NH
#define MX  (B*S)       // 4096 rows of x
#define MKV (B*NV)      // 3136 rows of fv
#define MDEC (B*(S-1))  // 4080 rows of dec

// ---------------- scratch (device globals; no allocation) ----------------
__device__ float g_x   [MX * D];
__device__ float g_qkv [MX * 3*D];
__device__ float g_attn[MX * D];
__device__ float g_y   [MX * D];
__device__ float g_q   [MX * D];
__device__ float g_kv  [MKV * 2*D];
__device__ float g_dec [MDEC * D];

// ---------------- helpers ----------------
__device__ __forceinline__ float to_tf32(float x) {
    uint32_t u;
    asm("cvt.rna.tf32.f32 %0, %1;" : "=r"(u) : "f"(x));
    return __uint_as_float(u);
}

__device__ __forceinline__ void mma_tf32(float c[4],
    uint32_t a0, uint32_t a1, uint32_t a2, uint32_t a3,
    uint32_t b0, uint32_t b1)
{
    asm volatile(
        "mma.sync.aligned.m16n8k8.row.col.f32.tf32.tf32.f32 "
        "{%0,%1,%2,%3},{%4,%5,%6,%7},{%8,%9},{%0,%1,%2,%3};\n"
        : "+f"(c[0]), "+f"(c[1]), "+f"(c[2]), "+f"(c[3])
        : "r"(a0), "r"(a1), "r"(a2), "r"(a3), "r"(b0), "r"(b1));
}

__device__ __forceinline__ void ldsm_x4(uint32_t& r0, uint32_t& r1,
                                        uint32_t& r2, uint32_t& r3, uint32_t addr)
{
    asm volatile("ldmatrix.sync.aligned.m8n8.x4.shared.b16 {%0,%1,%2,%3}, [%4];"
        : "=r"(r0), "=r"(r1), "=r"(r2), "=r"(r3) : "r"(addr));
}

__device__ __forceinline__ uint32_t smem_u32(const void* p) {
    return (uint32_t)__cvta_generic_to_shared(p);
}

// ---------------- add positional encoding ----------------
__global__ void add_pe_kernel(float* __restrict__ x, const float* __restrict__ te) {
    int row = blockIdx.x;
    int s   = row % S;
    int tid = threadIdx.x;
    size_t base = (size_t)row * D;
    #pragma unroll
    for (int i = 0; i < 3; i++) {
        int d = tid + i * 256;
        int i2 = d & ~1;
        float div = expf(-(float)i2 * (9.210340371976184f / (float)D));
        float ang = (float)s * div;
        float pe  = (d & 1) ? cosf(ang) : sinf(ang);
        x[base + d] = te[base + d] + pe;
    }
}

// ---------------- TF32 tensor-core GEMM (ldmatrix fragments) ----------------
// C[m][n] = sum_k A[m][k]*W[n][k] + bias[n] ; optional relu.
// Block tile 128x128, BK=32, 8 warps (2x4), warp tile 64x32.
// K must be a multiple of 32 (768, 2048 both are).
#define BM 128
#define BN 128
#define BK 32
#define LDK (BK + 4)     // 36 floats per row -> conflict-free fragments/ldmatrix
__global__ __launch_bounds__(256, 2) void tf32_gemm_kernel(
    const float* __restrict__ A, const float* __restrict__ W,
    const float* __restrict__ bias, float* __restrict__ C,
    int M, int N, int K, int relu)
{
    __shared__ float As[BM * LDK];
    __shared__ float Bs[BN * LDK];

    int tid  = threadIdx.x;
    int lane = tid & 31;
    int wid  = tid >> 5;
    int gid  = lane >> 2;     // group id 0..7
    int tig  = lane & 3;      // thread in group 0..3
    int wm   = wid >> 2;      // 0..1  -> m offset wm*64
    int wn   = wid & 3;       // 0..3  -> n offset wn*32

    int row0 = blockIdx.y * BM;
    int col0 = blockIdx.x * BN;

    // ldmatrix base addresses (kk-invariant part), one per A m-tile / B n-pair.
    // A fragment (16x8): tiles t0..t3 = (rows 0-7,k0-3)(rows 8-15,k0-3)(rows 0-7,k4-7)(rows 8-15,k4-7)
    //   lanes 0-15 -> row = base + (lane&15), col = 0 ; lanes 16-31 -> row = base + (lane&15), col = 4
    uint32_t a_base[4];
    #pragma unroll
    for (int mt = 0; mt < 4; mt++) {
        int arow = wm * 64 + mt * 16 + (lane & 15);
        int acol = (lane >> 4) << 2;
        a_base[mt] = smem_u32(&As[arow * LDK + acol]);
    }
    // B pair (16 n-rows x 8 k): t0=(n0-7,k0-3) t1=(n0-7,k4-7) t2=(n8-15,k0-3) t3=(n8-15,k4-7)
    uint32_t b_base[2];
    #pragma unroll
    for (int np = 0; np < 2; np++) {
        int brow = wn * 32 + np * 16 + (lane & 7) + ((lane >> 4) << 3);
        int bcol = ((lane >> 3) & 1) << 2;
        b_base[np] = smem_u32(&Bs[brow * LDK + bcol]);
    }

    // loader mapping: 128 rows x 8 float4 (BK=32) = 1024 float4 per operand; 4 per thread
    int lrow[4], lkv[4];
    #pragma unroll
    for (int i = 0; i < 4; i++) { int idx = i * 256 + tid; lrow[i] = idx >> 3; lkv[i] = idx & 7; }

    float4 ra[4], rb[4];
    // prefetch first k-tile
    #pragma unroll
    for (int i = 0; i < 4; i++) {
        int gr = row0 + lrow[i];
        int gk = lkv[i] * 4;
        if (gr < M) ra[i] = *(const float4*)&A[(size_t)gr * K + gk];
        else        ra[i] = make_float4(0.f, 0.f, 0.f, 0.f);
        int gn = col0 + lrow[i];
        if (gn < N) rb[i] = *(const float4*)&W[(size_t)gn * K + gk];
        else        rb[i] = make_float4(0.f, 0.f, 0.f, 0.f);
    }

    float acc[4][4][4] = {};   // [mtile][ntile][reg]

    for (int k0 = 0; k0 < K; k0 += BK) {
        // store prefetched tile to smem (tf32-rounded)
        #pragma unroll
        for (int i = 0; i < 4; i++) {
            float4 a4 = ra[i], b4 = rb[i];
            a4.x = to_tf32(a4.x); a4.y = to_tf32(a4.y); a4.z = to_tf32(a4.z); a4.w = to_tf32(a4.w);
            b4.x = to_tf32(b4.x); b4.y = to_tf32(b4.y); b4.z = to_tf32(b4.z); b4.w = to_tf32(b4.w);
            *(float4*)&As[lrow[i] * LDK + lkv[i] * 4] = a4;
            *(float4*)&Bs[lrow[i] * LDK + lkv[i] * 4] = b4;
        }
        __syncthreads();
        // prefetch next k-tile
        if (k0 + BK < K) {
            #pragma unroll
            for (int i = 0; i < 4; i++) {
                int gr = row0 + lrow[i];
                int gk = k0 + BK + lkv[i] * 4;
                if (gr < M) ra[i] = *(const float4*)&A[(size_t)gr * K + gk];
                else        ra[i] = make_float4(0.f, 0.f, 0.f, 0.f);
                int gn = col0 + lrow[i];
                if (gn < N) rb[i] = *(const float4*)&W[(size_t)gn * K + gk];
                else        rb[i] = make_float4(0.f, 0.f, 0.f, 0.f);
            }
        }
        // compute: 4 mma-k steps of 8, ldmatrix fragment loads
        #pragma unroll
        for (int kk = 0; kk < BK; kk += 8) {
            uint32_t af[4][4];
            #pragma unroll
            for (int mt = 0; mt < 4; mt++)
                ldsm_x4(af[mt][0], af[mt][1], af[mt][2], af[mt][3],
                        a_base[mt] + kk * 4);
            uint32_t bf[4][2];
            #pragma unroll
            for (int np = 0; np < 2; np++)
                ldsm_x4(bf[2*np][0], bf[2*np][1], bf[2*np+1][0], bf[2*np+1][1],
                        b_base[np] + kk * 4);
            #pragma unroll
            for (int mt = 0; mt < 4; mt++)
                #pragma unroll
                for (int nt = 0; nt < 4; nt++)
                    mma_tf32(acc[mt][nt], af[mt][0], af[mt][1], af[mt][2], af[mt][3],
                             bf[nt][0], bf[nt][1]);
        }
        __syncthreads();
    }

    // epilogue: c0:(gid, 2tig) c1:(gid, 2tig+1) c2:(gid+8, 2tig) c3:(gid+8, 2tig+1)
    #pragma unroll
    for (int mt = 0; mt < 4; mt++) {
        int r_lo = row0 + wm * 64 + mt * 16 + gid;
        int r_hi = r_lo + 8;
        #pragma unroll
        for (int nt = 0; nt < 4; nt++) {
            int gn = col0 + wn * 32 + nt * 8 + 2 * tig;
            if (gn >= N) continue;
            float b0 = bias ? bias[gn]     : 0.f;
            float b1 = bias ? bias[gn + 1] : 0.f;
            if (r_lo < M) {
                float v0 = acc[mt][nt][0] + b0;
                float v1 = acc[mt][nt][1] + b1;
                if (relu) { v0 = fmaxf(v0, 0.f); v1 = fmaxf(v1, 0.f); }
                *(float2*)&C[(size_t)r_lo * N + gn] = make_float2(v0, v1);
            }
            if (r_hi < M) {
                float v2 = acc[mt][nt][2] + b0;
                float v3 = acc[mt][nt][3] + b1;
                if (relu) { v2 = fmaxf(v2, 0.f); v3 = fmaxf(v3, 0.f); }
                *(float2*)&C[(size_t)r_hi * N + gn] = make_float2(v2, v3);
            }
        }
    }
}

static inline void launch_gemm(const float* A, const float* W, const float* bias,
                               float* C, int M, int N, int K, int relu) {
    dim3 grid((N + BN - 1) / BN, (M + BM - 1) / BM);
    tf32_gemm_kernel<<<grid, 256>>>(A, W, bias, C, M, N, K, relu);
}

// ---------------- flash attention: 32-q x 32-k tiles, online softmax ----------------
#define QT 32
#define KT 32
__global__ __launch_bounds__(256) void flash_attn_kernel(
    const float* __restrict__ Q, int q_stride,
    const float* __restrict__ KV, int kv_stride, int k_off, int v_off,
    float* __restrict__ O,
    int Lq, int Lk, int causal, float scale)
{
    __shared__ float Qs[QT][HD + 1];
    __shared__ float Ks[KT][HD + 1];
    __shared__ float Vs[KT][HD + 1];
    int bh = blockIdx.y;
    int b = bh >> 3, h = bh & 7;
    int q0 = blockIdx.x * QT;
    int tid = threadIdx.x;
    int qr = tid >> 3;         // 0..31 query row in tile
    int sub = tid & 7;         // 8 threads per row
    int qi = q0 + qr;

    const float* qbase = Q + (size_t)(b * Lq + q0) * q_stride + h * HD;
    for (int i = tid; i < QT * HD; i += 256) {
        int r = i / HD, d = i % HD;
        Qs[r][d] = qbase[(size_t)r * q_stride + d];
    }
    __syncthreads();

    const float* kbase = KV + (size_t)b * Lk * kv_stride + k_off + h * HD;
    const float* vbase = KV + (size_t)b * Lk * kv_stride + v_off + h * HD;

    float m = -1e30f, lsum = 0.f;
    float o[12];
    #pragma unroll
    for (int j = 0; j < 12; j++) o[j] = 0.f;

    int kend = causal ? (q0 + QT < Lk ? q0 + QT : Lk) : Lk;
    int lanebase = (tid & 31) & ~7;

    for (int k0 = 0; k0 < kend; k0 += KT) {
        for (int i = tid; i < KT * HD; i += 256) {
            int r = i / HD, d = i % HD;
            int ki = k0 + r;
            if (ki < Lk) {
                Ks[r][d] = kbase[(size_t)ki * kv_stride + d];
                Vs[r][d] = vbase[(size_t)ki * kv_stride + d];
            } else {
                Ks[r][d] = 0.f;
                Vs[r][d] = 0.f;
            }
        }
        __syncthreads();

        float sc[4];
        #pragma unroll
        for (int c = 0; c < 4; c++) {
            int kk = sub * 4 + c;
            int ki = k0 + kk;
            float acc = 0.f;
            #pragma unroll
            for (int d = 0; d < HD; d += 4) {
                acc = fmaf(Qs[qr][d + 0], Ks[kk][d + 0], acc);
                acc = fmaf(Qs[qr][d + 1], Ks[kk][d + 1], acc);
                acc = fmaf(Qs[qr][d + 2], Ks[kk][d + 2], acc);
                acc = fmaf(Qs[qr][d + 3], Ks[kk][d + 3], acc);
            }
            acc *= scale;
            if (ki >= Lk || (causal && ki > qi)) acc = -1e30f;
            sc[c] = acc;
        }
        float tm = fmaxf(fmaxf(sc[0], sc[1]), fmaxf(sc[2], sc[3]));
        #pragma unroll
        for (int off = 4; off; off >>= 1) tm = fmaxf(tm, __shfl_xor_sync(~0u, tm, off));
        float mnew = fmaxf(m, tm);
        float corr = __expf(m - mnew);
        float p[4];
        float psum = 0.f;
        #pragma unroll
        for (int c = 0; c < 4; c++) { p[c] = __expf(sc[c] - mnew); psum += p[c]; }
        #pragma unroll
        for (int off = 4; off; off >>= 1) psum += __shfl_xor_sync(~0u, psum, off);
        lsum = lsum * corr + psum;
        #pragma unroll
        for (int j = 0; j < 12; j++) o[j] *= corr;
        m = mnew;
        #pragma unroll
        for (int kk = 0; kk < KT; kk++) {
            float pv = __shfl_sync(~0u, p[kk & 3], lanebase + (kk >> 2));
            #pragma unroll
            for (int j = 0; j < 12; j++)
                o[j] = fmaf(pv, Vs[kk][sub * 12 + j], o[j]);
        }
        __syncthreads();
    }

    float inv = 1.f / lsum;
    float* orow = O + (size_t)(b * Lq + qi) * D + h * HD + sub * 12;
    #pragma unroll
    for (int j = 0; j < 12; j++) orow[j] = o[j] * inv;
}

// ---------------- fused residual + layernorm ----------------
__global__ __launch_bounds__(256) void residual_ln_kernel(
    float* __restrict__ X, const float* __restrict__ Y,
    const float* __restrict__ w, const float* __restrict__ b)
{
    __shared__ float red[8];
    int row = blockIdx.x;
    int tid = threadIdx.x;
    size_t base = (size_t)row * D;
    float v0 = X[base + tid]       + Y[base + tid];
    float v1 = X[base + tid + 256] + Y[base + tid + 256];
    float v2 = X[base + tid + 512] + Y[base + tid + 512];
    float s = v0 + v1 + v2;
    #pragma unroll
    for (int off = 16; off; off >>= 1) s += __shfl_xor_sync(~0u, s, off);
    if ((tid & 31) == 0) red[tid >> 5] = s;
    __syncthreads();
    float tot = 0.f;
    #pragma unroll
    for (int i = 0; i < 8; i++) tot += red[i];
    float mean = tot * (1.f / (float)D);
    float d0 = v0 - mean, d1 = v1 - mean, d2 = v2 - mean;
    float q = d0 * d0 + d1 * d1 + d2 * d2;
    #pragma unroll
    for (int off = 16; off; off >>= 1) q += __shfl_xor_sync(~0u, q, off);
    __syncthreads();
    if ((tid & 31) == 0) red[tid >> 5] = q;
    __syncthreads();
    float vq = 0.f;
    #pragma unroll
    for (int i = 0; i < 8; i++) vq += red[i];
    float var = vq * (1.f / (float)D);
    float rs = rsqrtf(var + 1e-5f);
    X[base + tid]       = d0 * rs * w[tid]       + b[tid];
    X[base + tid + 256] = d1 * rs * w[tid + 256] + b[tid + 256];
    X[base + tid + 512] = d2 * rs * w[tid + 512] + b[tid + 512];
}

// ---------------- dec copy ----------------
__global__ void copy_dec_kernel(float* __restrict__ dec, const float* __restrict__ x) {
    int r   = blockIdx.x;
    int b   = r / (S - 1);
    int s   = r % (S - 1);
    int tid = threadIdx.x;
    size_t src = (size_t)(b * S + s) * D;
    size_t dst = (size_t)r * D;
    #pragma unroll
    for (int i = 0; i < 3; i++) dec[dst + tid + i * 256] = x[src + tid + i * 256];
}

// ---------------- row softmax over D for F_t ----------------
__global__ __launch_bounds__(256) void softmax_rows_kernel(
    const float* __restrict__ X, float* __restrict__ O)
{
    __shared__ float red[8];
    int row = blockIdx.x;
    int tid = threadIdx.x;
    size_t base = (size_t)row * D;
    float v0 = X[base + tid], v1 = X[base + tid + 256], v2 = X[base + tid + 512];
    float m = fmaxf(fmaxf(v0, v1), v2);
    #pragma unroll
    for (int off = 16; off; off >>= 1) m = fmaxf(m, __shfl_xor_sync(~0u, m, off));
    if ((tid & 31) == 0) red[tid >> 5] = m;
    __syncthreads();
    float gm = red[0];
    #pragma unroll
    for (int i = 1; i < 8; i++) gm = fmaxf(gm, red[i]);
    float e0 = expf(v0 - gm), e1 = expf(v1 - gm), e2 = expf(v2 - gm);
    float s = e0 + e1 + e2;
    #pragma unroll
    for (int off = 16; off; off >>= 1) s += __shfl_xor_sync(~0u, s, off);
    __syncthreads();
    if ((tid & 31) == 0) red[tid >> 5] = s;
    __syncthreads();
    float tot = 0.f;
    #pragma unroll
    for (int i = 0; i < 8; i++) tot += red[i];
    float inv = 1.f / tot;
    O[base + tid]       = e0 * inv;
    O[base + tid + 256] = e1 * inv;
    O[base + tid + 512] = e2 * inv;
}

// ---------------- orchestration ----------------
extern "C" void kernel_launch(void* const* d_in, const int* in_sizes, int n_in,
                              void* d_out, int out_size)
{
    const float* fv          = (const float*)d_in[0];
    const float* target_embed= (const float*)d_in[1];
    const float* self_in_w   = (const float*)d_in[2];
    const float* self_in_b   = (const float*)d_in[3];
    const float* self_out_w  = (const float*)d_in[4];
    const float* self_out_b  = (const float*)d_in[5];
    const float* cross_in_w  = (const float*)d_in[6];
    const float* cross_in_b  = (const float*)d_in[7];
    const float* cross_out_w = (const float*)d_in[8];
    const float* cross_out_b = (const float*)d_in[9];
    const float* lin1_w      = (const float*)d_in[10];
    const float* lin1_b      = (const float*)d_in[11];
    const float* lin2_w      = (const float*)d_in[12];
    const float* lin2_b      = (const float*)d_in[13];
    const float* ln_w        = (const float*)d_in[14];
    const float* ln_b        = (const float*)d_in[15];
    const float* fc_out_w    = (const float*)d_in[16];
    float* out = (float*)d_out;

    float *px, *pqkv, *pattn, *py, *pq, *pkv, *pdec;
    cudaGetSymbolAddress((void**)&px,   g_x);
    cudaGetSymbolAddress((void**)&pqkv, g_qkv);
    cudaGetSymbolAddress((void**)&pattn,g_attn);
    cudaGetSymbolAddress((void**)&py,   g_y);
    cudaGetSymbolAddress((void**)&pq,   g_q);
    cudaGetSymbolAddress((void**)&pkv,  g_kv);
    cudaGetSymbolAddress((void**)&pdec, g_dec);

    const float scale = rsqrtf((float)HD);

    add_pe_kernel<<<MX, 256>>>(px, target_embed);

    for (int l = 0; l < NL; l++) {
        const float* siw = self_in_w   + (size_t)l * 3*D * D;
        const float* sib = self_in_b   + (size_t)l * 3*D;
        const float* sow = self_out_w  + (size_t)l * D * D;
        const float* sob = self_out_b  + (size_t)l * D;
        const float* ciw = cross_in_w  + (size_t)l * 3*D * D;
        const float* cib = cross_in_b  + (size_t)l * 3*D;
        const float* cow = cross_out_w + (size_t)l * D * D;
        const float* cob = cross_out_b + (size_t)l * D;
        const float* l1w = lin1_w      + (size_t)l * FF * D;
        const float* l1b = lin1_b      + (size_t)l * FF;
        const float* l2w = lin2_w      + (size_t)l * D * FF;
        const float* l2b = lin2_b      + (size_t)l * D;
        const float* lnw = ln_w        + (size_t)l * 3 * D;
        const float* lnb = ln_b        + (size_t)l * 3 * D;

        // ---- self attention ----
        launch_gemm(px, siw, sib, pqkv, MX, 3*D, D, 0);
        flash_attn_kernel<<<dim3(S / QT, B * NH), 256>>>(
            pqkv, 3*D, pqkv, 3*D, D, 2*D, pattn, S, S, 1, scale);
        launch_gemm(pattn, sow, sob, py, MX, D, D, 0);
        residual_ln_kernel<<<MX, 256>>>(px, py, lnw + 0*D, lnb + 0*D);

        // ---- cross attention ----
        launch_gemm(px, ciw, cib, pq, MX, D, D, 0);
        launch_gemm(fv, ciw + (size_t)D*D, cib + D, pkv, MKV, 2*D, D, 0);
        flash_attn_kernel<<<dim3(S / QT, B * NH), 256>>>(
            pq, D, pkv, 2*D, 0, D, pattn, S, NV, 0, scale);
        launch_gemm(pattn, cow, cob, py, MX, D, D, 0);
        residual_ln_kernel<<<MX, 256>>>(px, py, lnw + 1*D, lnb + 1*D);

        // ---- feed forward ----
        launch_gemm(px, l1w, l1b, pqkv, MX, FF, D, 1);
        launch_gemm(pqkv, l2w, l2b, py, MX, D, FF, 0);
        residual_ln_kernel<<<MX, 256>>>(px, py, lnw + 2*D, lnb + 2*D);
    }

    // ---- final heads ----
    copy_dec_kernel<<<MDEC, 256>>>(pdec, px);
    launch_gemm(pdec, fc_out_w, nullptr, out, MDEC, VOC, D, 0);
    softmax_rows_kernel<<<MDEC, 256>>>(pdec, out + (size_t)MDEC * VOC);
}

// round 17
// speedup vs baseline: 1.4072x; 1.0335x over previous
#include <cuda_runtime.h>
#include <cuda_bf16.h>
#include <math.h>
#include <stdint.h>

// ---------------- problem constants ----------------
#define B   16
#define S   256
#define NV  196
#define D   768
#define FF  2048
#define VOC 30522
#define NL  6
#define NH  8
#define HD  96          // D / NH
#define MX  (B*S)       // 4096 rows of x
#define MKV (B*NV)      // 3136 rows of fv
#define MDEC (B*(S-1))  // 4080 rows of dec

// weight-conversion scratch offsets (floats)
#define SIW_N (NL*3*D*D)          // 10616832
#define SOW_N (NL*D*D)            // 3538944
#define CIW_N (NL*3*D*D)          // 10616832
#define COW_N (NL*D*D)            // 3538944
#define L1W_N (NL*FF*D)           // 9437184
#define L2W_N (NL*D*FF)           // 9437184
#define FC_N  (VOC*D)             // 23440896
#define OFF_SIW 0
#define OFF_SOW (OFF_SIW + SIW_N)
#define OFF_CIW (OFF_SOW + SOW_N)
#define OFF_COW (OFF_CIW + CIW_N)
#define OFF_L1W (OFF_COW + COW_N)
#define OFF_L2W (OFF_L1W + L1W_N)
#define OFF_FC  (OFF_L2W + L2W_N)
#define WR_TOTAL (OFF_FC + FC_N)  // 70626816 floats

// ---------------- scratch (device globals; no allocation) ----------------
__device__ float g_x   [MX * D];        // running activation (full fp32)
__device__ float g_xr  [MX * D];        // tf32-rounded copy of x
__device__ float g_qkv [MX * 3*D];      // qkv / FF hidden (hidden stored rounded)
__device__ float g_attn[MX * D];        // attention out (stored rounded)
__device__ float g_y   [MX * D];        // sublayer out (full)
__device__ float g_q   [MX * D];        // cross-attn Q (full; attention input)
__device__ float g_kv  [MKV * 2*D];     // cross K,V (full; attention input)
__device__ float g_dec [MDEC * D];      // dec full (softmax input)
__device__ float g_decr[MDEC * D];      // dec rounded (logits GEMM input)
__device__ float g_fvr [MKV * D];       // fv rounded (crossKV GEMM input)
__device__ float g_wr  [WR_TOTAL];      // all weights tf32-rounded

// ---------------- helpers ----------------
__device__ __forceinline__ float to_tf32(float x) {
    uint32_t u;
    asm("cvt.rna.tf32.f32 %0, %1;" : "=r"(u) : "f"(x));
    return __uint_as_float(u);
}

__device__ __forceinline__ void mma_tf32(float c[4],
    uint32_t a0, uint32_t a1, uint32_t a2, uint32_t a3,
    uint32_t b0, uint32_t b1)
{
    asm volatile(
        "mma.sync.aligned.m16n8k8.row.col.f32.tf32.tf32.f32 "
        "{%0,%1,%2,%3},{%4,%5,%6,%7},{%8,%9},{%0,%1,%2,%3};\n"
        : "+f"(c[0]), "+f"(c[1]), "+f"(c[2]), "+f"(c[3])
        : "r"(a0), "r"(a1), "r"(a2), "r"(a3), "r"(b0), "r"(b1));
}

__device__ __forceinline__ void ldsm_x4(uint32_t& r0, uint32_t& r1,
                                        uint32_t& r2, uint32_t& r3, uint32_t addr)
{
    asm volatile("ldmatrix.sync.aligned.m8n8.x4.shared.b16 {%0,%1,%2,%3}, [%4];"
        : "=r"(r0), "=r"(r1), "=r"(r2), "=r"(r3) : "r"(addr));
}

__device__ __forceinline__ uint32_t smem_u32(const void* p) {
    return (uint32_t)__cvta_generic_to_shared(p);
}

__device__ __forceinline__ void cp_async16(uint32_t dst, const void* src, bool pred) {
    int b = pred ? 16 : 0;
    asm volatile("cp.async.cg.shared.global [%0], [%1], 16, %2;\n"
        :: "r"(dst), "l"(src), "r"(b));
}
#define CP_COMMIT() asm volatile("cp.async.commit_group;\n" ::: "memory")
#define CP_WAIT0()  asm volatile("cp.async.wait_group 0;\n" ::: "memory")

// ---------------- tf32 conversion (grid-stride, float4) ----------------
__global__ void cvt_tf32_kernel(float4* __restrict__ dst,
                                const float4* __restrict__ src, int n4)
{
    int i = blockIdx.x * blockDim.x + threadIdx.x;
    int stride = gridDim.x * blockDim.x;
    for (; i < n4; i += stride) {
        float4 v = src[i];
        v.x = to_tf32(v.x); v.y = to_tf32(v.y);
        v.z = to_tf32(v.z); v.w = to_tf32(v.w);
        dst[i] = v;
    }
}

// ---------------- add positional encoding (writes full + rounded) ----------------
__global__ void add_pe_kernel(float* __restrict__ x, float* __restrict__ xr,
                              const float* __restrict__ te) {
    int row = blockIdx.x;
    int s   = row % S;
    int tid = threadIdx.x;
    size_t base = (size_t)row * D;
    #pragma unroll
    for (int i = 0; i < 3; i++) {
        int d = tid + i * 256;
        int i2 = d & ~1;
        float div = expf(-(float)i2 * (9.210340371976184f / (float)D));
        float ang = (float)s * div;
        float pe  = (d & 1) ? cosf(ang) : sinf(ang);
        float v = te[base + d] + pe;
        x[base + d]  = v;
        xr[base + d] = to_tf32(v);
    }
}

// ---------------- TF32 tensor-core GEMM: 64x64x32, cp.async 2-stage ----------------
// C[m][n] = sum_k A[m][k]*W[n][k] + bias[n]; optional relu; optional tf32-rounded store.
// A and W must already be tf32-rounded. K must be a multiple of 32.
#define BM 64
#define BN 64
#define BK 32
#define LDK 36                  // 36 % 32 == 4 -> conflict-free ldmatrix
#define OPF (BM * LDK)          // 2304 floats per operand per stage
#define STG_BYTES (2 * OPF * 4) // 18432 bytes per stage (A then B)

__global__ __launch_bounds__(128, 6) void tf32_gemm_kernel(
    const float* __restrict__ A, const float* __restrict__ W,
    const float* __restrict__ bias, float* __restrict__ C,
    int M, int N, int K, int relu, int round_out)
{
    __shared__ float smbuf[2 * 2 * OPF];   // [A0 B0 A1 B1]
    uint32_t sm0 = smem_u32(smbuf);

    int tid  = threadIdx.x;
    int lane = tid & 31;
    int wid  = tid >> 5;          // 4 warps
    int gid  = lane >> 2;
    int tig  = lane & 3;
    int wm   = wid >> 1;          // 0..1 -> m offset wm*32
    int wn   = wid & 1;           // 0..1 -> n offset wn*32

    int row0 = blockIdx.y * BM;
    int col0 = blockIdx.x * BN;

    // ldmatrix base addresses (stage 0), validated layout from R10
    uint32_t a_base[2];
    #pragma unroll
    for (int mt = 0; mt < 2; mt++) {
        int arow = wm * 32 + mt * 16 + (lane & 15);
        int acol = (lane >> 4) << 2;
        a_base[mt] = sm0 + (uint32_t)(arow * LDK + acol) * 4;
    }
    uint32_t b_base[2];
    #pragma unroll
    for (int np = 0; np < 2; np++) {
        int brow = wn * 32 + np * 16 + (lane & 7) + ((lane >> 4) << 3);
        int bcol = ((lane >> 3) & 1) << 2;
        b_base[np] = sm0 + (uint32_t)(OPF * 4) + (uint32_t)(brow * LDK + bcol) * 4;
    }

    // loader mapping: 64 rows x 8 float4 per operand = 512; 4 per thread per operand
    int lrow[4], lkv[4];
    #pragma unroll
    for (int i = 0; i < 4; i++) { int idx = i * 128 + tid; lrow[i] = idx >> 3; lkv[i] = idx & 7; }

    // prologue: async-load tile 0 into stage 0
    #pragma unroll
    for (int i = 0; i < 4; i++) {
        int gr = row0 + lrow[i];
        bool p = gr < M;
        const float* src = &A[(size_t)(p ? gr : 0) * K + lkv[i] * 4];
        cp_async16(sm0 + (uint32_t)(lrow[i] * LDK + lkv[i] * 4) * 4, src, p);
    }
    #pragma unroll
    for (int i = 0; i < 4; i++) {
        int gn = col0 + lrow[i];
        bool p = gn < N;
        const float* src = &W[(size_t)(p ? gn : 0) * K + lkv[i] * 4];
        cp_async16(sm0 + (uint32_t)(OPF * 4) + (uint32_t)(lrow[i] * LDK + lkv[i] * 4) * 4, src, p);
    }
    CP_COMMIT();

    float acc[2][4][4] = {};   // [mtile][ntile][reg]
    int nT = K / BK;

    for (int t = 0; t < nT; t++) {
        CP_WAIT0();            // stage t data arrived
        __syncthreads();       // visible to all; prior compute finished

        if (t + 1 < nT) {      // async-load next tile into other stage (overlaps compute)
            int kb = (t + 1) * BK;
            uint32_t sb = sm0 + (uint32_t)(((t + 1) & 1) * STG_BYTES);
            #pragma unroll
            for (int i = 0; i < 4; i++) {
                int gr = row0 + lrow[i];
                bool p = gr < M;
                const float* src = &A[(size_t)(p ? gr : 0) * K + kb + lkv[i] * 4];
                cp_async16(sb + (uint32_t)(lrow[i] * LDK + lkv[i] * 4) * 4, src, p);
            }
            #pragma unroll
            for (int i = 0; i < 4; i++) {
                int gn = col0 + lrow[i];
                bool p = gn < N;
                const float* src = &W[(size_t)(p ? gn : 0) * K + kb + lkv[i] * 4];
                cp_async16(sb + (uint32_t)(OPF * 4) + (uint32_t)(lrow[i] * LDK + lkv[i] * 4) * 4, src, p);
            }
            CP_COMMIT();
        }

        uint32_t soff = (uint32_t)((t & 1) * STG_BYTES);
        #pragma unroll
        for (int kk = 0; kk < BK; kk += 8) {
            uint32_t af[2][4];
            #pragma unroll
            for (int mt = 0; mt < 2; mt++)
                ldsm_x4(af[mt][0], af[mt][1], af[mt][2], af[mt][3],
                        a_base[mt] + soff + kk * 4);
            uint32_t bf[4][2];
            #pragma unroll
            for (int np = 0; np < 2; np++)
                ldsm_x4(bf[2*np][0], bf[2*np][1], bf[2*np+1][0], bf[2*np+1][1],
                        b_base[np] + soff + kk * 4);
            #pragma unroll
            for (int mt = 0; mt < 2; mt++)
                #pragma unroll
                for (int nt = 0; nt < 4; nt++)
                    mma_tf32(acc[mt][nt], af[mt][0], af[mt][1], af[mt][2], af[mt][3],
                             bf[nt][0], bf[nt][1]);
        }
    }

    // epilogue
    #pragma unroll
    for (int mt = 0; mt < 2; mt++) {
        int r_lo = row0 + wm * 32 + mt * 16 + gid;
        int r_hi = r_lo + 8;
        #pragma unroll
        for (int nt = 0; nt < 4; nt++) {
            int gn = col0 + wn * 32 + nt * 8 + 2 * tig;
            if (gn >= N) continue;
            float b0 = bias ? bias[gn]     : 0.f;
            float b1 = bias ? bias[gn + 1] : 0.f;
            float v0 = acc[mt][nt][0] + b0;
            float v1 = acc[mt][nt][1] + b1;
            float v2 = acc[mt][nt][2] + b0;
            float v3 = acc[mt][nt][3] + b1;
            if (relu) {
                v0 = fmaxf(v0, 0.f); v1 = fmaxf(v1, 0.f);
                v2 = fmaxf(v2, 0.f); v3 = fmaxf(v3, 0.f);
            }
            if (round_out) {
                v0 = to_tf32(v0); v1 = to_tf32(v1);
                v2 = to_tf32(v2); v3 = to_tf32(v3);
            }
            if (r_lo < M) *(float2*)&C[(size_t)r_lo * N + gn] = make_float2(v0, v1);
            if (r_hi < M) *(float2*)&C[(size_t)r_hi * N + gn] = make_float2(v2, v3);
        }
    }
}

static inline void launch_gemm(const float* A, const float* W, const float* bias,
                               float* C, int M, int N, int K, int relu, int round_out) {
    dim3 grid((N + BN - 1) / BN, (M + BM - 1) / BM);
    tf32_gemm_kernel<<<grid, 128>>>(A, W, bias, C, M, N, K, relu, round_out);
}

// ---------------- flash attention (output stored tf32-rounded) ----------------
#define QT 32
#define KT 32
__global__ __launch_bounds__(256) void flash_attn_kernel(
    const float* __restrict__ Q, int q_stride,
    const float* __restrict__ KV, int kv_stride, int k_off, int v_off,
    float* __restrict__ O,
    int Lq, int Lk, int causal, float scale)
{
    __shared__ float Qs[QT][HD + 1];
    __shared__ float Ks[KT][HD + 1];
    __shared__ float Vs[KT][HD + 1];
    int bh = blockIdx.y;
    int b = bh >> 3, h = bh & 7;
    int q0 = blockIdx.x * QT;
    int tid = threadIdx.x;
    int qr = tid >> 3;
    int sub = tid & 7;
    int qi = q0 + qr;

    const float* qbase = Q + (size_t)(b * Lq + q0) * q_stride + h * HD;
    for (int i = tid; i < QT * HD; i += 256) {
        int r = i / HD, d = i % HD;
        Qs[r][d] = qbase[(size_t)r * q_stride + d];
    }
    __syncthreads();

    const float* kbase = KV + (size_t)b * Lk * kv_stride + k_off + h * HD;
    const float* vbase = KV + (size_t)b * Lk * kv_stride + v_off + h * HD;

    float m = -1e30f, lsum = 0.f;
    float o[12];
    #pragma unroll
    for (int j = 0; j < 12; j++) o[j] = 0.f;

    int kend = causal ? (q0 + QT < Lk ? q0 + QT : Lk) : Lk;
    int lanebase = (tid & 31) & ~7;

    for (int k0 = 0; k0 < kend; k0 += KT) {
        for (int i = tid; i < KT * HD; i += 256) {
            int r = i / HD, d = i % HD;
            int ki = k0 + r;
            if (ki < Lk) {
                Ks[r][d] = kbase[(size_t)ki * kv_stride + d];
                Vs[r][d] = vbase[(size_t)ki * kv_stride + d];
            } else {
                Ks[r][d] = 0.f;
                Vs[r][d] = 0.f;
            }
        }
        __syncthreads();

        float sc[4];
        #pragma unroll
        for (int c = 0; c < 4; c++) {
            int kk = sub * 4 + c;
            int ki = k0 + kk;
            float acc = 0.f;
            #pragma unroll
            for (int d = 0; d < HD; d += 4) {
                acc = fmaf(Qs[qr][d + 0], Ks[kk][d + 0], acc);
                acc = fmaf(Qs[qr][d + 1], Ks[kk][d + 1], acc);
                acc = fmaf(Qs[qr][d + 2], Ks[kk][d + 2], acc);
                acc = fmaf(Qs[qr][d + 3], Ks[kk][d + 3], acc);
            }
            acc *= scale;
            if (ki >= Lk || (causal && ki > qi)) acc = -1e30f;
            sc[c] = acc;
        }
        float tm = fmaxf(fmaxf(sc[0], sc[1]), fmaxf(sc[2], sc[3]));
        #pragma unroll
        for (int off = 4; off; off >>= 1) tm = fmaxf(tm, __shfl_xor_sync(~0u, tm, off));
        float mnew = fmaxf(m, tm);
        float corr = __expf(m - mnew);
        float p[4];
        float psum = 0.f;
        #pragma unroll
        for (int c = 0; c < 4; c++) { p[c] = __expf(sc[c] - mnew); psum += p[c]; }
        #pragma unroll
        for (int off = 4; off; off >>= 1) psum += __shfl_xor_sync(~0u, psum, off);
        lsum = lsum * corr + psum;
        #pragma unroll
        for (int j = 0; j < 12; j++) o[j] *= corr;
        m = mnew;
        #pragma unroll
        for (int kk = 0; kk < KT; kk++) {
            float pv = __shfl_sync(~0u, p[kk & 3], lanebase + (kk >> 2));
            #pragma unroll
            for (int j = 0; j < 12; j++)
                o[j] = fmaf(pv, Vs[kk][sub * 12 + j], o[j]);
        }
        __syncthreads();
    }

    float inv = 1.f / lsum;
    float* orow = O + (size_t)(b * Lq + qi) * D + h * HD + sub * 12;
    #pragma unroll
    for (int j = 0; j < 12; j++) orow[j] = to_tf32(o[j] * inv);
}

// ---------------- fused residual + layernorm (writes full + rounded) ----------------
__global__ __launch_bounds__(256) void residual_ln_kernel(
    float* __restrict__ X, float* __restrict__ Xr, const float* __restrict__ Y,
    const float* __restrict__ w, const float* __restrict__ b)
{
    __shared__ float red[8];
    int row = blockIdx.x;
    int tid = threadIdx.x;
    size_t base = (size_t)row * D;
    float v0 = X[base + tid]       + Y[base + tid];
    float v1 = X[base + tid + 256] + Y[base + tid + 256];
    float v2 = X[base + tid + 512] + Y[base + tid + 512];
    float s = v0 + v1 + v2;
    #pragma unroll
    for (int off = 16; off; off >>= 1) s += __shfl_xor_sync(~0u, s, off);
    if ((tid & 31) == 0) red[tid >> 5] = s;
    __syncthreads();
    float tot = 0.f;
    #pragma unroll
    for (int i = 0; i < 8; i++) tot += red[i];
    float mean = tot * (1.f / (float)D);
    float d0 = v0 - mean, d1 = v1 - mean, d2 = v2 - mean;
    float q = d0 * d0 + d1 * d1 + d2 * d2;
    #pragma unroll
    for (int off = 16; off; off >>= 1) q += __shfl_xor_sync(~0u, q, off);
    __syncthreads();
    if ((tid & 31) == 0) red[tid >> 5] = q;
    __syncthreads();
    float vq = 0.f;
    #pragma unroll
    for (int i = 0; i < 8; i++) vq += red[i];
    float var = vq * (1.f / (float)D);
    float rs = rsqrtf(var + 1e-5f);
    float o0 = d0 * rs * w[tid]       + b[tid];
    float o1 = d1 * rs * w[tid + 256] + b[tid + 256];
    float o2 = d2 * rs * w[tid + 512] + b[tid + 512];
    X[base + tid]        = o0;
    X[base + tid + 256]  = o1;
    X[base + tid + 512]  = o2;
    Xr[base + tid]       = to_tf32(o0);
    Xr[base + tid + 256] = to_tf32(o1);
    Xr[base + tid + 512] = to_tf32(o2);
}

// ---------------- dec copy (full + rounded) ----------------
__global__ void copy_dec_kernel(float* __restrict__ dec, float* __restrict__ decr,
                                const float* __restrict__ x) {
    int r   = blockIdx.x;
    int b   = r / (S - 1);
    int s   = r % (S - 1);
    int tid = threadIdx.x;
    size_t src = (size_t)(b * S + s) * D;
    size_t dst = (size_t)r * D;
    #pragma unroll
    for (int i = 0; i < 3; i++) {
        float v = x[src + tid + i * 256];
        dec [dst + tid + i * 256] = v;
        decr[dst + tid + i * 256] = to_tf32(v);
    }
}

// ---------------- row softmax over D for F_t ----------------
__global__ __launch_bounds__(256) void softmax_rows_kernel(
    const float* __restrict__ X, float* __restrict__ O)
{
    __shared__ float red[8];
    int row = blockIdx.x;
    int tid = threadIdx.x;
    size_t base = (size_t)row * D;
    float v0 = X[base + tid], v1 = X[base + tid + 256], v2 = X[base + tid + 512];
    float m = fmaxf(fmaxf(v0, v1), v2);
    #pragma unroll
    for (int off = 16; off; off >>= 1) m = fmaxf(m, __shfl_xor_sync(~0u, m, off));
    if ((tid & 31) == 0) red[tid >> 5] = m;
    __syncthreads();
    float gm = red[0];
    #pragma unroll
    for (int i = 1; i < 8; i++) gm = fmaxf(gm, red[i]);
    float e0 = expf(v0 - gm), e1 = expf(v1 - gm), e2 = expf(v2 - gm);
    float s = e0 + e1 + e2;
    #pragma unroll
    for (int off = 16; off; off >>= 1) s += __shfl_xor_sync(~0u, s, off);
    __syncthreads();
    if ((tid & 31) == 0) red[tid >> 5] = s;
    __syncthreads();
    float tot = 0.f;
    #pragma unroll
    for (int i = 0; i < 8; i++) tot += red[i];
    float inv = 1.f / tot;
    O[base + tid]       = e0 * inv;
    O[base + tid + 256] = e1 * inv;
    O[base + tid + 512] = e2 * inv;
}

// ---------------- orchestration ----------------
extern "C" void kernel_launch(void* const* d_in, const int* in_sizes, int n_in,
                              void* d_out, int out_size)
{
    const float* fv          = (const float*)d_in[0];
    const float* target_embed= (const float*)d_in[1];
    const float* self_in_w   = (const float*)d_in[2];
    const float* self_in_b   = (const float*)d_in[3];
    const float* self_out_w  = (const float*)d_in[4];
    const float* self_out_b  = (const float*)d_in[5];
    const float* cross_in_w  = (const float*)d_in[6];
    const float* cross_in_b  = (const float*)d_in[7];
    const float* cross_out_w = (const float*)d_in[8];
    const float* cross_out_b = (const float*)d_in[9];
    const float* lin1_w      = (const float*)d_in[10];
    const float* lin1_b      = (const float*)d_in[11];
    const float* lin2_w      = (const float*)d_in[12];
    const float* lin2_b      = (const float*)d_in[13];
    const float* ln_w        = (const float*)d_in[14];
    const float* ln_b        = (const float*)d_in[15];
    const float* fc_out_w    = (const float*)d_in[16];
    float* out = (float*)d_out;

    float *px, *pxr, *pqkv, *pattn, *py, *pq, *pkv, *pdec, *pdecr, *pfvr, *pwr;
    cudaGetSymbolAddress((void**)&px,    g_x);
    cudaGetSymbolAddress((void**)&pxr,   g_xr);
    cudaGetSymbolAddress((void**)&pqkv,  g_qkv);
    cudaGetSymbolAddress((void**)&pattn, g_attn);
    cudaGetSymbolAddress((void**)&py,    g_y);
    cudaGetSymbolAddress((void**)&pq,    g_q);
    cudaGetSymbolAddress((void**)&pkv,   g_kv);
    cudaGetSymbolAddress((void**)&pdec,  g_dec);
    cudaGetSymbolAddress((void**)&pdecr, g_decr);
    cudaGetSymbolAddress((void**)&pfvr,  g_fvr);
    cudaGetSymbolAddress((void**)&pwr,   g_wr);

    const float scale = rsqrtf((float)HD);

    // ---- pre-round all weights + fv into scratch (tf32 rna) ----
    cvt_tf32_kernel<<<1024, 256>>>((float4*)(pwr + OFF_SIW), (const float4*)self_in_w,  SIW_N / 4);
    cvt_tf32_kernel<<<1024, 256>>>((float4*)(pwr + OFF_SOW), (const float4*)self_out_w, SOW_N / 4);
    cvt_tf32_kernel<<<1024, 256>>>((float4*)(pwr + OFF_CIW), (const float4*)cross_in_w, CIW_N / 4);
    cvt_tf32_kernel<<<1024, 256>>>((float4*)(pwr + OFF_COW), (const float4*)cross_out_w,COW_N / 4);
    cvt_tf32_kernel<<<1024, 256>>>((float4*)(pwr + OFF_L1W), (const float4*)lin1_w,     L1W_N / 4);
    cvt_tf32_kernel<<<1024, 256>>>((float4*)(pwr + OFF_L2W), (const float4*)lin2_w,     L2W_N / 4);
    cvt_tf32_kernel<<<1024, 256>>>((float4*)(pwr + OFF_FC),  (const float4*)fc_out_w,   FC_N / 4);
    cvt_tf32_kernel<<<1024, 256>>>((float4*)pfvr,            (const float4*)fv,         (MKV * D) / 4);

    // x = target_embed + PE (full + rounded)
    add_pe_kernel<<<MX, 256>>>(px, pxr, target_embed);

    for (int l = 0; l < NL; l++) {
        const float* siw = pwr + OFF_SIW + (size_t)l * 3*D * D;
        const float* sow = pwr + OFF_SOW + (size_t)l * D * D;
        const float* ciw = pwr + OFF_CIW + (size_t)l * 3*D * D;
        const float* cow = pwr + OFF_COW + (size_t)l * D * D;
        const float* l1w = pwr + OFF_L1W + (size_t)l * FF * D;
        const float* l2w = pwr + OFF_L2W + (size_t)l * D * FF;
        const float* sib = self_in_b   + (size_t)l * 3*D;
        const float* sob = self_out_b  + (size_t)l * D;
        const float* cib = cross_in_b  + (size_t)l * 3*D;
        const float* cob = cross_out_b + (size_t)l * D;
        const float* l1b = lin1_b      + (size_t)l * FF;
        const float* l2b = lin2_b      + (size_t)l * D;
        const float* lnw = ln_w        + (size_t)l * 3 * D;
        const float* lnb = ln_b        + (size_t)l * 3 * D;

        // ---- self attention ----
        launch_gemm(pxr, siw, sib, pqkv, MX, 3*D, D, 0, 0);
        flash_attn_kernel<<<dim3(S / QT, B * NH), 256>>>(
            pqkv, 3*D, pqkv, 3*D, D, 2*D, pattn, S, S, 1, scale);   // out rounded
        launch_gemm(pattn, sow, sob, py, MX, D, D, 0, 0);
        residual_ln_kernel<<<MX, 256>>>(px, pxr, py, lnw + 0*D, lnb + 0*D);

        // ---- cross attention ----
        launch_gemm(pxr, ciw, cib, pq, MX, D, D, 0, 0);                         // Q (first D rows)
        launch_gemm(pfvr, ciw + (size_t)D*D, cib + D, pkv, MKV, 2*D, D, 0, 0);  // K,V
        flash_attn_kernel<<<dim3(S / QT, B * NH), 256>>>(
            pq, D, pkv, 2*D, 0, D, pattn, S, NV, 0, scale);          // out rounded
        launch_gemm(pattn, cow, cob, py, MX, D, D, 0, 0);
        residual_ln_kernel<<<MX, 256>>>(px, pxr, py, lnw + 1*D, lnb + 1*D);

        // ---- feed forward (hidden stored rounded for FF2) ----
        launch_gemm(pxr, l1w, l1b, pqkv, MX, FF, D, 1, 1);
        launch_gemm(pqkv, l2w, l2b, py, MX, D, FF, 0, 0);
        residual_ln_kernel<<<MX, 256>>>(px, pxr, py, lnw + 2*D, lnb + 2*D);
    }

    // ---- final heads ----
    copy_dec_kernel<<<MDEC, 256>>>(pdec, pdecr, px);
    launch_gemm(pdecr, pwr + OFF_FC, nullptr, out, MDEC, VOC, D, 0, 0);
    softmax_rows_kernel<<<MDEC, 256>>>(pdec, out + (size_t)MDEC * VOC);
}